// round 5
// baseline (speedup 1.0000x reference)
#include <cuda_runtime.h>

typedef unsigned long long ull;

#define HID 10
#define BATCH 16384
#define TPAIRS 1024
#define TPB 128

// ---------- constant-bank weights (packed, pre-scaled) ----------
// layout (longlong2 entries):
//  [0..99]    whB   [j*10+q] : pairs of gates (4q..4q+3) for h[j]
//  [100..199] whA
//  [200..209] wxB0  [q]
//  [210..219] wxA0
//  [220..229] wxA1
//  [230..239] bB    (bih+bhh fused)
//  [240..249] bA
#define OFF_WHB  0
#define OFF_WHA  100
#define OFF_WXB  200
#define OFF_WXA0 210
#define OFF_WXA1 220
#define OFF_BB   230
#define OFF_BA   240

__constant__ longlong2 c_w[250];
__device__   longlong2 g_pack[250];

// ---------- packed fp32x2 helpers ----------
__device__ __forceinline__ ull pack2(float lo, float hi){
    ull r; asm("mov.b64 %0, {%1, %2};" : "=l"(r) : "f"(lo), "f"(hi)); return r;
}
__device__ __forceinline__ ull bcast2(float v){
    ull r; asm("mov.b64 %0, {%1, %1};" : "=l"(r) : "f"(v)); return r;
}
__device__ __forceinline__ void unpack2(ull v, float &lo, float &hi){
    asm("mov.b64 {%0, %1}, %2;" : "=f"(lo), "=f"(hi) : "l"(v));
}
__device__ __forceinline__ ull ffma2(ull a, ull b, ull c){
    ull d; asm("fma.rn.f32x2 %0, %1, %2, %3;" : "=l"(d) : "l"(a), "l"(b), "l"(c)); return d;
}
__device__ __forceinline__ float tanh_ap(float x){
    float r; asm("tanh.approx.f32 %0, %1;" : "=f"(r) : "f"(x)); return r;
}

// gate scale: 0.5 for i/f/o rows (sigmoid via 0.5*tanh(z/2)+0.5), 1.0 for g rows
__device__ __forceinline__ float gsc(int g){ return (g >= 20 && g < 30) ? 1.0f : 0.5f; }

// ---------- pack kernel: global weights -> g_pack (then D2D memcpy to c_w) ----------
__global__ void pack_kernel(
    const float* __restrict__ WihA, const float* __restrict__ WhhA,
    const float* __restrict__ bihA, const float* __restrict__ bhhA,
    const float* __restrict__ WihB, const float* __restrict__ WhhB,
    const float* __restrict__ bihB, const float* __restrict__ bhhB)
{
    int idx = threadIdx.x;
    if (idx < 200){
        int cell = idx / 100;          // 0 = B, 1 = A
        int rem  = idx % 100;          // j*10 + q
        int j = rem / 10, q = rem % 10;
        int g0 = 4 * q;
        const float* W = cell ? WhhA : WhhB;
        g_pack[(cell ? OFF_WHA : OFF_WHB) + rem] = make_longlong2(
            (long long)pack2(gsc(g0+0)*W[(g0+0)*HID + j], gsc(g0+1)*W[(g0+1)*HID + j]),
            (long long)pack2(gsc(g0+2)*W[(g0+2)*HID + j], gsc(g0+3)*W[(g0+3)*HID + j]));
    } else if (idx < 250){
        int k = idx - 200;
        int grp = k / 10, q = k % 10;
        int g0 = 4 * q;
        longlong2 v;
        if (grp == 0){        // wxB0 (WihB is [40,1])
            v = make_longlong2(
                (long long)pack2(gsc(g0+0)*WihB[g0+0], gsc(g0+1)*WihB[g0+1]),
                (long long)pack2(gsc(g0+2)*WihB[g0+2], gsc(g0+3)*WihB[g0+3]));
        } else if (grp == 1){ // wxA0 (WihA is [40,2])
            v = make_longlong2(
                (long long)pack2(gsc(g0+0)*WihA[(g0+0)*2], gsc(g0+1)*WihA[(g0+1)*2]),
                (long long)pack2(gsc(g0+2)*WihA[(g0+2)*2], gsc(g0+3)*WihA[(g0+3)*2]));
        } else if (grp == 2){ // wxA1
            v = make_longlong2(
                (long long)pack2(gsc(g0+0)*WihA[(g0+0)*2+1], gsc(g0+1)*WihA[(g0+1)*2+1]),
                (long long)pack2(gsc(g0+2)*WihA[(g0+2)*2+1], gsc(g0+3)*WihA[(g0+3)*2+1]));
        } else if (grp == 3){ // bB
            v = make_longlong2(
                (long long)pack2(gsc(g0+0)*(bihB[g0+0]+bhhB[g0+0]), gsc(g0+1)*(bihB[g0+1]+bhhB[g0+1])),
                (long long)pack2(gsc(g0+2)*(bihB[g0+2]+bhhB[g0+2]), gsc(g0+3)*(bihB[g0+3]+bhhB[g0+3])));
        } else {              // bA
            v = make_longlong2(
                (long long)pack2(gsc(g0+0)*(bihA[g0+0]+bhhA[g0+0]), gsc(g0+1)*(bihA[g0+1]+bhhA[g0+1])),
                (long long)pack2(gsc(g0+2)*(bihA[g0+2]+bhhA[g0+2]), gsc(g0+3)*(bihA[g0+3]+bhhA[g0+3])));
        }
        g_pack[idx] = v;
    }
}

// ---------- one LSTM cell step; all weights from constant bank ----------
// WH/WX0/WX1/BI are compile-time constant-bank offsets -> literal const
// addresses after unroll -> uniform-path LDCU (no LSU traffic).
template<int NIN, int WH, int WX0, int WX1, int BI>
__device__ __forceinline__ void cell_step(float h[HID], float c[HID], float x0, float x1)
{
    ull acc[20];
#pragma unroll
    for (int q = 0; q < 10; q++){
        acc[2*q]   = (ull)c_w[BI + q].x;
        acc[2*q+1] = (ull)c_w[BI + q].y;
    }
#pragma unroll
    for (int j = 0; j < HID; j++){
        ull hb = bcast2(h[j]);
#pragma unroll
        for (int q = 0; q < 10; q++){
            acc[2*q]   = ffma2((ull)c_w[WH + j*10 + q].x, hb, acc[2*q]);
            acc[2*q+1] = ffma2((ull)c_w[WH + j*10 + q].y, hb, acc[2*q+1]);
        }
    }
    {
        ull xb = bcast2(x0);
#pragma unroll
        for (int q = 0; q < 10; q++){
            acc[2*q]   = ffma2((ull)c_w[WX0 + q].x, xb, acc[2*q]);
            acc[2*q+1] = ffma2((ull)c_w[WX0 + q].y, xb, acc[2*q+1]);
        }
    }
    if (NIN == 2){
        ull xb = bcast2(x1);
#pragma unroll
        for (int q = 0; q < 10; q++){
            acc[2*q]   = ffma2((ull)c_w[WX1 + q].x, xb, acc[2*q]);
            acc[2*q+1] = ffma2((ull)c_w[WX1 + q].y, xb, acc[2*q+1]);
        }
    }
    float g[40];
#pragma unroll
    for (int q = 0; q < 20; q++) unpack2(acc[q], g[2*q], g[2*q+1]);
    // g[0..9]=i' (half-scaled), g[10..19]=f' (half-scaled), g[20..29]=g, g[30..39]=o'
#pragma unroll
    for (int d = 0; d < HID; d++){
        float si = fmaf(0.5f, tanh_ap(g[d]),         0.5f);
        float sf = fmaf(0.5f, tanh_ap(g[HID + d]),   0.5f);
        float tg = tanh_ap(g[2*HID + d]);
        float so = fmaf(0.5f, tanh_ap(g[3*HID + d]), 0.5f);
        float cn = fmaf(sf, c[d], si * tg);
        c[d] = cn;
        h[d] = so * tanh_ap(cn);
    }
}

__global__ void __launch_bounds__(TPB, 1)
multicell_lstm_kernel(
    const float* __restrict__ x,
    const float* __restrict__ Wlin, const float* __restrict__ blin,
    float* __restrict__ out)
{
    const int b = blockIdx.x * TPB + threadIdx.x;

    const float4* xp = reinterpret_cast<const float4*>(x) + (size_t)b * TPAIRS;

    float h[HID], c[HID];
#pragma unroll
    for (int d = 0; d < HID; d++){ h[d] = 0.0f; c[d] = 0.0f; }

    for (int p = 0; p < TPAIRS; p++){
        float4 xv = __ldg(&xp[p]);
        cell_step<1, OFF_WHB, OFF_WXB,  OFF_WXB,  OFF_BB>(h, c, xv.x, 0.0f);
        cell_step<2, OFF_WHA, OFF_WXA0, OFF_WXA1, OFF_BA>(h, c, xv.z, xv.w);
    }

    float a = __ldg(&blin[0]);
#pragma unroll
    for (int d = 0; d < HID; d++) a = fmaf(h[d], __ldg(&Wlin[d]), a);
    out[b] = fmaf(0.5f, tanh_ap(0.5f * a), 0.5f);
}

extern "C" void kernel_launch(void* const* d_in, const int* in_sizes, int n_in,
                              void* d_out, int out_size)
{
    const float* x    = (const float*)d_in[0];
    const float* WihA = (const float*)d_in[1];
    const float* WhhA = (const float*)d_in[2];
    const float* bihA = (const float*)d_in[3];
    const float* bhhA = (const float*)d_in[4];
    const float* WihB = (const float*)d_in[5];
    const float* WhhB = (const float*)d_in[6];
    const float* bihB = (const float*)d_in[7];
    const float* bhhB = (const float*)d_in[8];
    const float* Wlin = (const float*)d_in[9];
    const float* blin = (const float*)d_in[10];
    float* out = (float*)d_out;

    // 1) pack weights into device scratch
    pack_kernel<<<1, 256>>>(WihA, WhhA, bihA, bhhA, WihB, WhhB, bihB, bhhB);

    // 2) D2D copy into constant bank. NOTE: src must be the *device address*
    //    of g_pack — resolving it via cudaGetSymbolAddress (pure query, capture-safe).
    //    Passing `g_pack` directly passes the host shadow address (r4 bug).
    void* g_pack_dev = nullptr;
    cudaGetSymbolAddress(&g_pack_dev, g_pack);
    cudaMemcpyToSymbolAsync(c_w, g_pack_dev, 250 * sizeof(longlong2), 0,
                            cudaMemcpyDeviceToDevice, 0);

    // 3) main recurrent kernel, weights from uniform constant path
    dim3 grid(BATCH / TPB), block(TPB);
    multicell_lstm_kernel<<<grid, block>>>(x, Wlin, blin, out);
}

// round 6
// speedup vs baseline: 1.4885x; 1.4885x over previous
#include <cuda_runtime.h>

typedef unsigned long long ull;

#define HID 10
#define BATCH 16384
#define TPAIRS 1024
#define TPB 128

// ---------- constant-bank layout (longlong2 entries), same as r5 ----------
//  [0..99]    whB   [j*10+q] : pairs of gates (4q..4q+3) for h[j]
//  [100..199] whA
//  [200..209] wxB0
//  [210..219] wxA0
//  [220..229] wxA1
//  [230..239] bB (bih+bhh fused)
//  [240..249] bA
#define OFF_WHB  0
#define OFF_WHA  100
#define OFF_WXB  200
#define OFF_WXA0 210
#define OFF_WXA1 220
#define OFF_BB   230
#define OFF_BA   240

__constant__ longlong2 c_w[250];
__device__   longlong2 g_pack[250];

// ---------- packed fp32x2 helpers ----------
__device__ __forceinline__ ull pack2(float lo, float hi){
    ull r; asm("mov.b64 %0, {%1, %2};" : "=l"(r) : "f"(lo), "f"(hi)); return r;
}
__device__ __forceinline__ ull bcast2(float v){
    ull r; asm("mov.b64 %0, {%1, %1};" : "=l"(r) : "f"(v)); return r;
}
__device__ __forceinline__ void unpack2(ull v, float &lo, float &hi){
    asm("mov.b64 {%0, %1}, %2;" : "=f"(lo), "=f"(hi) : "l"(v));
}
__device__ __forceinline__ ull ffma2(ull a, ull b, ull c){
    ull d; asm("fma.rn.f32x2 %0, %1, %2, %3;" : "=l"(d) : "l"(a), "l"(b), "l"(c)); return d;
}
__device__ __forceinline__ float tanh_ap(float x){
    float r; asm("tanh.approx.f32 %0, %1;" : "=f"(r) : "f"(x)); return r;
}

// gate scale: 0.5 for i/f/o rows (sigmoid via 0.5*tanh(z/2)+0.5), 1.0 for g rows
__device__ __forceinline__ float gsc(int g){ return (g >= 20 && g < 30) ? 1.0f : 0.5f; }

// ---------- pack kernel (identical to r5, known-good) ----------
__global__ void pack_kernel(
    const float* __restrict__ WihA, const float* __restrict__ WhhA,
    const float* __restrict__ bihA, const float* __restrict__ bhhA,
    const float* __restrict__ WihB, const float* __restrict__ WhhB,
    const float* __restrict__ bihB, const float* __restrict__ bhhB)
{
    int idx = threadIdx.x;
    if (idx < 200){
        int cell = idx / 100;          // 0 = B, 1 = A
        int rem  = idx % 100;          // j*10 + q
        int j = rem / 10, q = rem % 10;
        int g0 = 4 * q;
        const float* W = cell ? WhhA : WhhB;
        g_pack[(cell ? OFF_WHA : OFF_WHB) + rem] = make_longlong2(
            (long long)pack2(gsc(g0+0)*W[(g0+0)*HID + j], gsc(g0+1)*W[(g0+1)*HID + j]),
            (long long)pack2(gsc(g0+2)*W[(g0+2)*HID + j], gsc(g0+3)*W[(g0+3)*HID + j]));
    } else if (idx < 250){
        int k = idx - 200;
        int grp = k / 10, q = k % 10;
        int g0 = 4 * q;
        longlong2 v;
        if (grp == 0){        // wxB0 (WihB is [40,1])
            v = make_longlong2(
                (long long)pack2(gsc(g0+0)*WihB[g0+0], gsc(g0+1)*WihB[g0+1]),
                (long long)pack2(gsc(g0+2)*WihB[g0+2], gsc(g0+3)*WihB[g0+3]));
        } else if (grp == 1){ // wxA0 (WihA is [40,2])
            v = make_longlong2(
                (long long)pack2(gsc(g0+0)*WihA[(g0+0)*2], gsc(g0+1)*WihA[(g0+1)*2]),
                (long long)pack2(gsc(g0+2)*WihA[(g0+2)*2], gsc(g0+3)*WihA[(g0+3)*2]));
        } else if (grp == 2){ // wxA1
            v = make_longlong2(
                (long long)pack2(gsc(g0+0)*WihA[(g0+0)*2+1], gsc(g0+1)*WihA[(g0+1)*2+1]),
                (long long)pack2(gsc(g0+2)*WihA[(g0+2)*2+1], gsc(g0+3)*WihA[(g0+3)*2+1]));
        } else if (grp == 3){ // bB
            v = make_longlong2(
                (long long)pack2(gsc(g0+0)*(bihB[g0+0]+bhhB[g0+0]), gsc(g0+1)*(bihB[g0+1]+bhhB[g0+1])),
                (long long)pack2(gsc(g0+2)*(bihB[g0+2]+bhhB[g0+2]), gsc(g0+3)*(bihB[g0+3]+bhhB[g0+3])));
        } else {              // bA
            v = make_longlong2(
                (long long)pack2(gsc(g0+0)*(bihA[g0+0]+bhhA[g0+0]), gsc(g0+1)*(bihA[g0+1]+bhhA[g0+1])),
                (long long)pack2(gsc(g0+2)*(bihA[g0+2]+bhhA[g0+2]), gsc(g0+3)*(bihA[g0+3]+bhhA[g0+3])));
        }
        g_pack[idx] = v;
    }
}

// ---------- dual-port LSTM cell step ----------
// h-rows j=0..4 and wx0 from SHARED (s_wh[j*10+q] j<5, s_wx[q]);
// h-rows j=5..9 and wx1 from CONSTANT (c_w[WHC + j*10 + q], c_w[WX1C + q]);
// biases live in registers. Both ports stream concurrently inside one step.
template<int NIN, int WHC, int WX1C>
__device__ __forceinline__ void cell_step(
    const longlong2* __restrict__ s_wh,   // 50 entries (j=0..4)
    const longlong2* __restrict__ s_wx,   // 10 entries
    const ull* bias,                      // 20 ull, register-resident
    float h[HID], float c[HID], float x0, float x1)
{
    ull acc[20];
#pragma unroll
    for (int q = 0; q < 20; q++) acc[q] = bias[q];

    // const-port rows (j = 5..9)
#pragma unroll
    for (int j = 5; j < 10; j++){
        ull hb = bcast2(h[j]);
#pragma unroll
        for (int q = 0; q < 10; q++){
            longlong2 w = c_w[WHC + j*10 + q];
            acc[2*q]   = ffma2((ull)w.x, hb, acc[2*q]);
            acc[2*q+1] = ffma2((ull)w.y, hb, acc[2*q+1]);
        }
    }
    // smem-port rows (j = 0..4)
#pragma unroll
    for (int j = 0; j < 5; j++){
        ull hb = bcast2(h[j]);
#pragma unroll
        for (int q = 0; q < 10; q++){
            longlong2 w = s_wh[j*10 + q];
            acc[2*q]   = ffma2((ull)w.x, hb, acc[2*q]);
            acc[2*q+1] = ffma2((ull)w.y, hb, acc[2*q+1]);
        }
    }
    // x contributions: x0 via smem, x1 via const
    {
        ull xb = bcast2(x0);
#pragma unroll
        for (int q = 0; q < 10; q++){
            longlong2 w = s_wx[q];
            acc[2*q]   = ffma2((ull)w.x, xb, acc[2*q]);
            acc[2*q+1] = ffma2((ull)w.y, xb, acc[2*q+1]);
        }
    }
    if (NIN == 2){
        ull xb = bcast2(x1);
#pragma unroll
        for (int q = 0; q < 10; q++){
            longlong2 w = c_w[WX1C + q];
            acc[2*q]   = ffma2((ull)w.x, xb, acc[2*q]);
            acc[2*q+1] = ffma2((ull)w.y, xb, acc[2*q+1]);
        }
    }

    float g[40];
#pragma unroll
    for (int q = 0; q < 20; q++) unpack2(acc[q], g[2*q], g[2*q+1]);
    // g[0..9]=i' (half-scaled), g[10..19]=f' (half-scaled), g[20..29]=g, g[30..39]=o'
#pragma unroll
    for (int d = 0; d < HID; d++){
        float si = fmaf(0.5f, tanh_ap(g[d]),         0.5f);
        float sf = fmaf(0.5f, tanh_ap(g[HID + d]),   0.5f);
        float tg = tanh_ap(g[2*HID + d]);
        float so = fmaf(0.5f, tanh_ap(g[3*HID + d]), 0.5f);
        float cn = fmaf(sf, c[d], si * tg);
        c[d] = cn;
        h[d] = so * tanh_ap(cn);
    }
}

__global__ void __launch_bounds__(TPB, 1)
multicell_lstm_kernel(
    const float* __restrict__ x,
    const float* __restrict__ Wlin, const float* __restrict__ blin,
    float* __restrict__ out)
{
    // smem subset: [0..49] whB j0-4, [50..99] whA j0-4, [100..109] wxB, [110..119] wxA0
    __shared__ longlong2 s_w[120];
    const int tid = threadIdx.x;
    for (int i = tid; i < 120; i += TPB){
        int src;
        if      (i < 50)  src = OFF_WHB  + i;
        else if (i < 100) src = OFF_WHA  + (i - 50);
        else if (i < 110) src = OFF_WXB  + (i - 100);
        else              src = OFF_WXA0 + (i - 110);
        s_w[i] = g_pack[src];
    }
    __syncthreads();

    // register-resident biases
    ull bB[20], bA[20];
#pragma unroll
    for (int q = 0; q < 10; q++){
        longlong2 vb = c_w[OFF_BB + q];
        longlong2 va = c_w[OFF_BA + q];
        bB[2*q] = (ull)vb.x; bB[2*q+1] = (ull)vb.y;
        bA[2*q] = (ull)va.x; bA[2*q+1] = (ull)va.y;
    }

    const int b = blockIdx.x * TPB + tid;
    const float4* xp = reinterpret_cast<const float4*>(x) + (size_t)b * TPAIRS;

    float h[HID], c[HID];
#pragma unroll
    for (int d = 0; d < HID; d++){ h[d] = 0.0f; c[d] = 0.0f; }

    for (int p = 0; p < TPAIRS; p++){
        float4 xv = __ldg(&xp[p]);
        cell_step<1, OFF_WHB, OFF_WXB >(s_w,      s_w + 100, bB, h, c, xv.x, 0.0f);
        cell_step<2, OFF_WHA, OFF_WXA1>(s_w + 50, s_w + 110, bA, h, c, xv.z, xv.w);
    }

    float a = __ldg(&blin[0]);
#pragma unroll
    for (int d = 0; d < HID; d++) a = fmaf(h[d], __ldg(&Wlin[d]), a);
    out[b] = fmaf(0.5f, tanh_ap(0.5f * a), 0.5f);
}

extern "C" void kernel_launch(void* const* d_in, const int* in_sizes, int n_in,
                              void* d_out, int out_size)
{
    const float* x    = (const float*)d_in[0];
    const float* WihA = (const float*)d_in[1];
    const float* WhhA = (const float*)d_in[2];
    const float* bihA = (const float*)d_in[3];
    const float* bhhA = (const float*)d_in[4];
    const float* WihB = (const float*)d_in[5];
    const float* WhhB = (const float*)d_in[6];
    const float* bihB = (const float*)d_in[7];
    const float* bhhB = (const float*)d_in[8];
    const float* Wlin = (const float*)d_in[9];
    const float* blin = (const float*)d_in[10];
    float* out = (float*)d_out;

    // 1) pack weights into device scratch
    pack_kernel<<<1, 256>>>(WihA, WhhA, bihA, bhhA, WihB, WhhB, bihB, bhhB);

    // 2) D2D copy into constant bank (src = resolved device address of g_pack)
    void* g_pack_dev = nullptr;
    cudaGetSymbolAddress(&g_pack_dev, g_pack);
    cudaMemcpyToSymbolAsync(c_w, g_pack_dev, 250 * sizeof(longlong2), 0,
                            cudaMemcpyDeviceToDevice, 0);

    // 3) main recurrent kernel: smem + const ports in parallel
    dim3 grid(BATCH / TPB), block(TPB);
    multicell_lstm_kernel<<<grid, block>>>(x, Wlin, blin, out);
}

// round 7
// speedup vs baseline: 1.5629x; 1.0499x over previous
#include <cuda_runtime.h>

typedef unsigned long long ull;

#define HID 10
#define BATCH 16384
#define TPAIRS 1024
#define TPB 256

// ---------- g_pack / c_w layout (250 longlong2, split-thread packing) ----------
// entry(cell, jj, r, p): absolute j = (jj<5)? 5r+jj : 5(1-r)+(jj-5); dim d = 5r+p
//   = ( pack2(0.5*W[d][j], 0.5*W[10+d][j]), pack2(W[20+d][j], 0.5*W[30+d][j]) )
// [0..79]    whB jj=0..7 : jj*10 + r*5 + p      (smem)
// [80..159]  whA jj=0..7                        (smem)
// [160..179] whB jj=8..9 : (jj-8)*10 + r*5 + p  (const)
// [180..199] whA jj=8..9                        (const)
// [200..209] wxB  [r*5+p]                       (smem)
// [210..219] wxA0                               (smem)
// [220..229] wxA1                               (const)
// [230..239] bB  (bih+bhh fused)                (const -> regs)
// [240..249] bA                                 (const -> regs)
#define OFF_WHB   0
#define OFF_WHA   80
#define OFF_WHB89 160
#define OFF_WHA89 180
#define OFF_WXB   200
#define OFF_WXA0  210
#define OFF_WXA1  220
#define OFF_BB    230
#define OFF_BA    240

__constant__ longlong2 c_w[250];
__device__   longlong2 g_pack[250];

// ---------- packed fp32x2 helpers ----------
__device__ __forceinline__ ull pack2(float lo, float hi){
    ull r; asm("mov.b64 %0, {%1, %2};" : "=l"(r) : "f"(lo), "f"(hi)); return r;
}
__device__ __forceinline__ ull bcast2(float v){
    ull r; asm("mov.b64 %0, {%1, %1};" : "=l"(r) : "f"(v)); return r;
}
__device__ __forceinline__ void unpack2(ull v, float &lo, float &hi){
    asm("mov.b64 {%0, %1}, %2;" : "=f"(lo), "=f"(hi) : "l"(v));
}
__device__ __forceinline__ ull ffma2(ull a, ull b, ull c){
    ull d; asm("fma.rn.f32x2 %0, %1, %2, %3;" : "=l"(d) : "l"(a), "l"(b), "l"(c)); return d;
}
__device__ __forceinline__ float tanh_ap(float x){
    float r; asm("tanh.approx.f32 %0, %1;" : "=f"(r) : "f"(x)); return r;
}

// ---------- pack kernel ----------
__global__ void pack_kernel(
    const float* __restrict__ WihA, const float* __restrict__ WhhA,
    const float* __restrict__ bihA, const float* __restrict__ bhhA,
    const float* __restrict__ WihB, const float* __restrict__ WhhB,
    const float* __restrict__ bihB, const float* __restrict__ bhhB)
{
    int idx = threadIdx.x;
    if (idx < 160){
        // wh jj = 0..7
        int cell = idx / 80;           // 0 = B, 1 = A
        int rem  = idx % 80;           // jj*10 + r*5 + p
        int jj = rem / 10;
        int r  = (rem % 10) / 5;
        int p  = rem % 5;
        int aj = (jj < 5) ? (5*r + jj) : (5*(1-r) + (jj-5));
        int d  = 5*r + p;
        const float* W = cell ? WhhA : WhhB;
        g_pack[(cell ? OFF_WHA : OFF_WHB) + rem] = make_longlong2(
            (long long)pack2(0.5f*W[(      d)*HID + aj], 0.5f*W[(  HID+d)*HID + aj]),
            (long long)pack2(     W[(2*HID+d)*HID + aj], 0.5f*W[(3*HID+d)*HID + aj]));
    } else if (idx < 200){
        // wh jj = 8..9 (const region)
        int k    = idx - 160;
        int cell = k / 20;
        int rem  = k % 20;             // (jj-8)*10 + r*5 + p
        int jj = 8 + rem / 10;
        int r  = (rem % 10) / 5;
        int p  = rem % 5;
        int aj = 5*(1-r) + (jj-5);
        int d  = 5*r + p;
        const float* W = cell ? WhhA : WhhB;
        g_pack[(cell ? OFF_WHA89 : OFF_WHB89) + rem] = make_longlong2(
            (long long)pack2(0.5f*W[(      d)*HID + aj], 0.5f*W[(  HID+d)*HID + aj]),
            (long long)pack2(     W[(2*HID+d)*HID + aj], 0.5f*W[(3*HID+d)*HID + aj]));
    } else if (idx < 250){
        int k = idx - 200;
        int grp = k / 10;              // 0 wxB, 1 wxA0, 2 wxA1, 3 bB, 4 bA
        int rp  = k % 10;              // r*5 + p
        int r = rp / 5, p = rp % 5;
        int d = 5*r + p;
        longlong2 v;
        if (grp == 0){
            v = make_longlong2(
                (long long)pack2(0.5f*WihB[d],         0.5f*WihB[HID+d]),
                (long long)pack2(     WihB[2*HID+d],   0.5f*WihB[3*HID+d]));
        } else if (grp == 1){
            v = make_longlong2(
                (long long)pack2(0.5f*WihA[(      d)*2], 0.5f*WihA[(  HID+d)*2]),
                (long long)pack2(     WihA[(2*HID+d)*2], 0.5f*WihA[(3*HID+d)*2]));
        } else if (grp == 2){
            v = make_longlong2(
                (long long)pack2(0.5f*WihA[(      d)*2+1], 0.5f*WihA[(  HID+d)*2+1]),
                (long long)pack2(     WihA[(2*HID+d)*2+1], 0.5f*WihA[(3*HID+d)*2+1]));
        } else if (grp == 3){
            v = make_longlong2(
                (long long)pack2(0.5f*(bihB[d]       + bhhB[d]),
                                 0.5f*(bihB[HID+d]   + bhhB[HID+d])),
                (long long)pack2(     (bihB[2*HID+d] + bhhB[2*HID+d]),
                                 0.5f*(bihB[3*HID+d] + bhhB[3*HID+d])));
        } else {
            v = make_longlong2(
                (long long)pack2(0.5f*(bihA[d]       + bhhA[d]),
                                 0.5f*(bihA[HID+d]   + bhhA[HID+d])),
                (long long)pack2(     (bihA[2*HID+d] + bhhA[2*HID+d]),
                                 0.5f*(bihA[3*HID+d] + bhhA[3*HID+d])));
        }
        g_pack[idx] = v;
    }
}

// ---------- dual-port split-thread LSTM cell step ----------
// 2 threads per element; thread r owns dims 5r..5r+4 (all 4 gates).
// smem: h-rows jj=0..7 (s_wh, 80 entries) + wx0 (s_wx0, 10 entries)
// const: h-rows jj=8..9 (c_w[WH89 + (jj-8)*10 + rbase + p]) + wx1 (NIN==2)
// biases: register-resident (bif/bgo, 5 ull each).
template<int NIN, int WH89, int WX1C>
__device__ __forceinline__ void cell_step(
    const longlong2* __restrict__ s_wh,
    const longlong2* __restrict__ s_wx0,
    const ull* bif, const ull* bgo,
    int rbase, float h[5], float c[5], float x0, float x1)
{
    // partner-h exchange first: shfl latency hides under subsequent matvec
    float hp[5];
#pragma unroll
    for (int p = 0; p < 5; p++) hp[p] = __shfl_xor_sync(0xffffffffu, h[p], 1);

    ull aIF[5], aGO[5];
#pragma unroll
    for (int p = 0; p < 5; p++){ aIF[p] = bif[p]; aGO[p] = bgo[p]; }

    // const-port rows jj = 8,9 (uses hp[3], hp[4]) — issue early (long latency)
#pragma unroll
    for (int jj = 8; jj < 10; jj++){
        ull hb = bcast2(hp[jj-5]);
#pragma unroll
        for (int p = 0; p < 5; p++){
            longlong2 w = c_w[WH89 + (jj-8)*10 + rbase + p];
            aIF[p] = ffma2((ull)w.x, hb, aIF[p]);
            aGO[p] = ffma2((ull)w.y, hb, aGO[p]);
        }
    }
    if (NIN == 2){
        ull xb = bcast2(x1);
#pragma unroll
        for (int p = 0; p < 5; p++){
            longlong2 w = c_w[WX1C + rbase + p];
            aIF[p] = ffma2((ull)w.x, xb, aIF[p]);
            aGO[p] = ffma2((ull)w.y, xb, aGO[p]);
        }
    }
    // smem x0
    {
        ull xb = bcast2(x0);
#pragma unroll
        for (int p = 0; p < 5; p++){
            longlong2 w = s_wx0[rbase + p];
            aIF[p] = ffma2((ull)w.x, xb, aIF[p]);
            aGO[p] = ffma2((ull)w.y, xb, aGO[p]);
        }
    }
    // smem own rows jj = 0..4
#pragma unroll
    for (int jj = 0; jj < 5; jj++){
        ull hb = bcast2(h[jj]);
#pragma unroll
        for (int p = 0; p < 5; p++){
            longlong2 w = s_wh[jj*10 + rbase + p];
            aIF[p] = ffma2((ull)w.x, hb, aIF[p]);
            aGO[p] = ffma2((ull)w.y, hb, aGO[p]);
        }
    }
    // smem partner rows jj = 5..7 (hp[0..2])
#pragma unroll
    for (int jj = 5; jj < 8; jj++){
        ull hb = bcast2(hp[jj-5]);
#pragma unroll
        for (int p = 0; p < 5; p++){
            longlong2 w = s_wh[jj*10 + rbase + p];
            aIF[p] = ffma2((ull)w.x, hb, aIF[p]);
            aGO[p] = ffma2((ull)w.y, hb, aGO[p]);
        }
    }
    // epilogue: 5 MUFU per owned dim
#pragma unroll
    for (int p = 0; p < 5; p++){
        float zi, zf, zg, zo;
        unpack2(aIF[p], zi, zf);
        unpack2(aGO[p], zg, zo);
        float si = fmaf(0.5f, tanh_ap(zi), 0.5f);
        float sf = fmaf(0.5f, tanh_ap(zf), 0.5f);
        float tg = tanh_ap(zg);
        float so = fmaf(0.5f, tanh_ap(zo), 0.5f);
        float cn = fmaf(sf, c[p], si * tg);
        c[p] = cn;
        h[p] = so * tanh_ap(cn);
    }
}

__global__ void __launch_bounds__(TPB, 1)
multicell_lstm_kernel(
    const float* __restrict__ x,
    const float* __restrict__ Wlin, const float* __restrict__ blin,
    float* __restrict__ out)
{
    // smem subset: [0..79] whB jj0-7, [80..159] whA jj0-7, [160..169] wxB, [170..179] wxA0
    __shared__ longlong2 s_w[180];
    const int tid = threadIdx.x;
    for (int i = tid; i < 180; i += TPB){
        int src;
        if      (i < 160) src = i;
        else if (i < 170) src = OFF_WXB  + (i - 160);
        else              src = OFF_WXA0 + (i - 170);
        s_w[i] = g_pack[src];
    }
    __syncthreads();

    const int rbase = (tid & 1) * 5;

    // register-resident biases (one divergent const read, once)
    ull bBif[5], bBgo[5], bAif[5], bAgo[5];
#pragma unroll
    for (int p = 0; p < 5; p++){
        longlong2 vb = c_w[OFF_BB + rbase + p];
        longlong2 va = c_w[OFF_BA + rbase + p];
        bBif[p] = (ull)vb.x; bBgo[p] = (ull)vb.y;
        bAif[p] = (ull)va.x; bAgo[p] = (ull)va.y;
    }

    const int e = (blockIdx.x * TPB + tid) >> 1;   // element id, 2 threads/element
    const float4* xp = reinterpret_cast<const float4*>(x) + (size_t)e * TPAIRS;

    float h[5], c[5];
#pragma unroll
    for (int p = 0; p < 5; p++){ h[p] = 0.0f; c[p] = 0.0f; }

    for (int p = 0; p < TPAIRS; p++){
        float4 xv = __ldg(&xp[p]);
        cell_step<1, OFF_WHB89, OFF_WXA1>(s_w,      s_w + 160, bBif, bBgo, rbase, h, c, xv.x, 0.0f);
        cell_step<2, OFF_WHA89, OFF_WXA1>(s_w + 80, s_w + 170, bAif, bAgo, rbase, h, c, xv.z, xv.w);
    }

    // out = sigmoid(h @ Wlin.T + blin): partial dot over owned dims + pair-sum
    float a = 0.0f;
#pragma unroll
    for (int p = 0; p < 5; p++) a = fmaf(h[p], __ldg(&Wlin[rbase + p]), a);
    a += __shfl_xor_sync(0xffffffffu, a, 1);
    if ((tid & 1) == 0)
        out[e] = fmaf(0.5f, tanh_ap(0.5f * (a + __ldg(&blin[0]))), 0.5f);
}

extern "C" void kernel_launch(void* const* d_in, const int* in_sizes, int n_in,
                              void* d_out, int out_size)
{
    const float* x    = (const float*)d_in[0];
    const float* WihA = (const float*)d_in[1];
    const float* WhhA = (const float*)d_in[2];
    const float* bihA = (const float*)d_in[3];
    const float* bhhA = (const float*)d_in[4];
    const float* WihB = (const float*)d_in[5];
    const float* WhhB = (const float*)d_in[6];
    const float* bihB = (const float*)d_in[7];
    const float* bhhB = (const float*)d_in[8];
    const float* Wlin = (const float*)d_in[9];
    const float* blin = (const float*)d_in[10];
    float* out = (float*)d_out;

    // 1) pack weights into device scratch
    pack_kernel<<<1, 256>>>(WihA, WhhA, bihA, bhhA, WihB, WhhB, bihB, bhhB);

    // 2) D2D copy into constant bank (src = resolved device address of g_pack)
    void* g_pack_dev = nullptr;
    cudaGetSymbolAddress(&g_pack_dev, g_pack);
    cudaMemcpyToSymbolAsync(c_w, g_pack_dev, 250 * sizeof(longlong2), 0,
                            cudaMemcpyDeviceToDevice, 0);

    // 3) main kernel: 2 threads/element -> 1024 warps = 2 warps/SMSP on 128 SMs
    dim3 grid((BATCH * 2) / TPB), block(TPB);
    multicell_lstm_kernel<<<grid, block>>>(x, Wlin, blin, out);
}